// round 2
// baseline (speedup 1.0000x reference)
#include <cuda_runtime.h>
#include <cstdint>

#define N_NODES 50000
#define D 128
#define EPS 0.001f

// Scratch (allocation-free rule: __device__ globals)
__device__ float g_h[(size_t)N_NODES * D];   // (1+eps)*x + segment_sum
__device__ float g_h1[(size_t)N_NODES * D];  // relu(h@W1+b1)
__device__ int   g_is64;                     // edge_index width flag

// ---------------------------------------------------------------------------
// Detect whether edge_index is int64 or int32 (JAX x64-flag ambiguity).
// If int64 (little-endian, values < 2^31), every odd int32 word is 0.
// ---------------------------------------------------------------------------
__global__ void detect_kernel(const int* __restrict__ e32) {
    if (threadIdx.x == 0 && blockIdx.x == 0) {
        int is64 = 1;
        #pragma unroll 1
        for (int k = 1; k < 128; k += 2) {
            if (e32[k] != 0) { is64 = 0; break; }
        }
        g_is64 = is64;
    }
}

// ---------------------------------------------------------------------------
// h = (1+eps) * x   (vectorized float4)
// ---------------------------------------------------------------------------
__global__ void init_h_kernel(const float* __restrict__ x, int n4) {
    int i = blockIdx.x * blockDim.x + threadIdx.x;
    if (i < n4) {
        float4 v = reinterpret_cast<const float4*>(x)[i];
        const float s = 1.0f + EPS;
        v.x *= s; v.y *= s; v.z *= s; v.w *= s;
        reinterpret_cast<float4*>(g_h)[i] = v;
    }
}

// ---------------------------------------------------------------------------
// Scatter-add: one warp per edge. Lane l handles floats [4l, 4l+4).
// Gather x[src] row (512B coalesced) and red.global.add.v4.f32 into h[dst].
// ---------------------------------------------------------------------------
__global__ void scatter_kernel(const float* __restrict__ x,
                               const void* __restrict__ ei, int E) {
    int w = (blockIdx.x * blockDim.x + threadIdx.x) >> 5;
    int lane = threadIdx.x & 31;
    if (w >= E) return;

    long long s, d;
    if (g_is64) {
        const long long* e = reinterpret_cast<const long long*>(ei);
        s = e[w];
        d = e[(size_t)E + w];
    } else {
        const int* e = reinterpret_cast<const int*>(ei);
        s = e[w];
        d = e[(size_t)E + w];
    }

    float4 v = *reinterpret_cast<const float4*>(x + (size_t)s * D + lane * 4);
    float* dst = g_h + (size_t)d * D + lane * 4;
    asm volatile("red.global.add.v4.f32 [%0], {%1, %2, %3, %4};"
                 :: "l"(dst), "f"(v.x), "f"(v.y), "f"(v.z), "f"(v.w)
                 : "memory");
}

// ---------------------------------------------------------------------------
// C[M,128] = act(A[M,128] @ B[128,128] + bias)
// Tile: 128 rows x 128 cols per block, 256 threads, 8x8 micro-tile.
// K streamed in chunks of 16 through SMEM (A stored k-major/transposed).
// ---------------------------------------------------------------------------
template <bool RELU>
__global__ void __launch_bounds__(256, 2)
gemm128_kernel(const float* __restrict__ A, const float* __restrict__ B,
               const float* __restrict__ bias, float* __restrict__ C, int M) {
    __shared__ float As[16][132];   // [k][m], padded vs bank conflicts
    __shared__ float Bs[16][128];   // [k][n]

    const int tx = threadIdx.x & 15;       // column group
    const int ty = threadIdx.x >> 4;       // row group
    const int row0 = blockIdx.x * 128 + ty * 8;
    const int col0 = tx * 8;

    float acc[8][8];
    #pragma unroll
    for (int i = 0; i < 8; i++)
        #pragma unroll
        for (int j = 0; j < 8; j++) acc[i][j] = 0.0f;

    for (int kk = 0; kk < 128; kk += 16) {
        // Cooperative loads: 512 float4 of A, 512 float4 of B.
        #pragma unroll
        for (int i = 0; i < 2; i++) {
            int f = threadIdx.x * 2 + i;          // 0..511
            // A: element block (m = f/4, float4 kq = f%4), transpose into As
            int m  = f >> 2;
            int kq = f & 3;
            int grow = blockIdx.x * 128 + m;
            float4 va = make_float4(0.f, 0.f, 0.f, 0.f);
            if (grow < M)
                va = *reinterpret_cast<const float4*>(A + (size_t)grow * D + kk + kq * 4);
            As[kq * 4 + 0][m] = va.x;
            As[kq * 4 + 1][m] = va.y;
            As[kq * 4 + 2][m] = va.z;
            As[kq * 4 + 3][m] = va.w;
            // B: row kb = f/32, float4 n4 = f%32
            int kb = f >> 5;
            int n4 = f & 31;
            float4 vb = *reinterpret_cast<const float4*>(B + (size_t)(kk + kb) * D + n4 * 4);
            *reinterpret_cast<float4*>(&Bs[kb][n4 * 4]) = vb;
        }
        __syncthreads();

        #pragma unroll
        for (int k = 0; k < 16; k++) {
            float a[8], b[8];
            #pragma unroll
            for (int i = 0; i < 8; i++) a[i] = As[k][ty * 8 + i];
            #pragma unroll
            for (int j = 0; j < 8; j++) b[j] = Bs[k][col0 + j];
            #pragma unroll
            for (int i = 0; i < 8; i++)
                #pragma unroll
                for (int j = 0; j < 8; j++)
                    acc[i][j] = fmaf(a[i], b[j], acc[i][j]);
        }
        __syncthreads();
    }

    float bv[8];
    #pragma unroll
    for (int j = 0; j < 8; j++) bv[j] = bias[col0 + j];

    #pragma unroll
    for (int i = 0; i < 8; i++) {
        int r = row0 + i;
        if (r < M) {
            float4 o0, o1;
            float v;
            v = acc[i][0] + bv[0]; o0.x = RELU ? fmaxf(v, 0.f) : v;
            v = acc[i][1] + bv[1]; o0.y = RELU ? fmaxf(v, 0.f) : v;
            v = acc[i][2] + bv[2]; o0.z = RELU ? fmaxf(v, 0.f) : v;
            v = acc[i][3] + bv[3]; o0.w = RELU ? fmaxf(v, 0.f) : v;
            v = acc[i][4] + bv[4]; o1.x = RELU ? fmaxf(v, 0.f) : v;
            v = acc[i][5] + bv[5]; o1.y = RELU ? fmaxf(v, 0.f) : v;
            v = acc[i][6] + bv[6]; o1.z = RELU ? fmaxf(v, 0.f) : v;
            v = acc[i][7] + bv[7]; o1.w = RELU ? fmaxf(v, 0.f) : v;
            *reinterpret_cast<float4*>(C + (size_t)r * D + col0)     = o0;
            *reinterpret_cast<float4*>(C + (size_t)r * D + col0 + 4) = o1;
        }
    }
}

extern "C" void kernel_launch(void* const* d_in, const int* in_sizes, int n_in,
                              void* d_out, int out_size) {
    const float* x  = (const float*)d_in[0];
    const void*  ei = d_in[1];
    const float* W1 = (const float*)d_in[2];
    const float* b1 = (const float*)d_in[3];
    const float* W2 = (const float*)d_in[4];
    const float* b2 = (const float*)d_in[5];
    float* out = (float*)d_out;

    const int N = in_sizes[0] / D;        // 50000
    const int E = in_sizes[1] / 2;        // 1600000 (row-major [2, E])

    // Resolve DEVICE addresses of the scratch symbols. (Passing `g_h` directly
    // from host code passes the host shadow address — on GB300 ATS makes that
    // silently readable as zeros, which was the R1 correctness bug.)
    float* h_dev  = nullptr;
    float* h1_dev = nullptr;
    cudaGetSymbolAddress((void**)&h_dev,  g_h);
    cudaGetSymbolAddress((void**)&h1_dev, g_h1);

    // 1) detect edge index width (deterministic each call)
    detect_kernel<<<1, 32>>>((const int*)ei);

    // 2) h = (1+eps)*x
    int n4 = N * (D / 4);
    init_h_kernel<<<(n4 + 255) / 256, 256>>>(x, n4);

    // 3) scatter-add: one warp per edge, 8 warps per block
    int sblocks = (E + 7) / 8;
    scatter_kernel<<<sblocks, 256>>>(x, ei, E);

    // 4) h1 = relu(h @ W1 + b1)
    int gblocks = (N + 127) / 128;
    gemm128_kernel<true><<<gblocks, 256>>>(h_dev, W1, b1, h1_dev, N);

    // 5) out = h1 @ W2 + b2
    gemm128_kernel<false><<<gblocks, 256>>>(h1_dev, W2, b2, out, N);
}

// round 4
// speedup vs baseline: 1.3663x; 1.3663x over previous
#include <cuda_runtime.h>
#include <cstdint>

#define N_NODES 50000
#define N_EDGES_MAX 1600000
#define D 128
#define EPS 0.001f

// Scratch (allocation-free rule: __device__ globals)
__device__ float g_h[(size_t)N_NODES * D];      // (1+eps)*x + segment_sum
__device__ int   g_degcnt[N_NODES];             // per-dst degree
__device__ int   g_off[N_NODES + 1];            // CSR offsets
__device__ int   g_cur[N_NODES];                // fill cursors
__device__ int   g_csrc[N_EDGES_MAX];           // src ids bucketed by dst
__device__ int   g_is64;                        // edge_index width flag

// ---------------------------------------------------------------------------
// Detect whether edge_index is int64 or int32 (JAX x64-flag ambiguity).
// ---------------------------------------------------------------------------
__global__ void detect_kernel(const int* __restrict__ e32) {
    if (threadIdx.x == 0 && blockIdx.x == 0) {
        int is64 = 1;
        #pragma unroll 1
        for (int k = 1; k < 128; k += 2) {
            if (e32[k] != 0) { is64 = 0; break; }
        }
        g_is64 = is64;
    }
}

__global__ void zero_deg_kernel(int* __restrict__ degcnt, int n) {
    int i = blockIdx.x * blockDim.x + threadIdx.x;
    if (i < n) degcnt[i] = 0;
}

// ---------------------------------------------------------------------------
// Histogram of dst
// ---------------------------------------------------------------------------
__global__ void hist_kernel(const void* __restrict__ ei, int E,
                            int* __restrict__ degcnt) {
    int i = blockIdx.x * blockDim.x + threadIdx.x;
    if (i >= E) return;
    int dd;
    if (g_is64) dd = (int)reinterpret_cast<const long long*>(ei)[(size_t)E + i];
    else        dd = reinterpret_cast<const int*>(ei)[(size_t)E + i];
    atomicAdd(degcnt + dd, 1);
}

// ---------------------------------------------------------------------------
// Exclusive prefix sum over degcnt[0..N) -> off[], cur[]. One block, 1024 thr.
// ---------------------------------------------------------------------------
__global__ void scan_kernel(const int* __restrict__ degcnt,
                            int* __restrict__ off,
                            int* __restrict__ cur, int N) {
    __shared__ int wsum[32];
    __shared__ int s_carry;
    const int tid = threadIdx.x, lane = tid & 31, wid = tid >> 5;
    if (tid == 0) s_carry = 0;
    __syncthreads();

    for (int base = 0; base < N; base += 1024) {
        int idx = base + tid;
        int v = (idx < N) ? degcnt[idx] : 0;
        int incl = v;
        #pragma unroll
        for (int o = 1; o < 32; o <<= 1) {
            int t = __shfl_up_sync(0xffffffffu, incl, o);
            if (lane >= o) incl += t;
        }
        if (lane == 31) wsum[wid] = incl;
        __syncthreads();
        if (wid == 0) {
            int s = wsum[lane];
            #pragma unroll
            for (int o = 1; o < 32; o <<= 1) {
                int t = __shfl_up_sync(0xffffffffu, s, o);
                if (lane >= o) s += t;
            }
            wsum[lane] = s;
        }
        __syncthreads();
        int carry = s_carry;
        int woff  = wid ? wsum[wid - 1] : 0;
        int excl  = carry + woff + incl - v;
        if (idx < N) { off[idx] = excl; cur[idx] = excl; }
        __syncthreads();
        if (tid == 0) s_carry = carry + wsum[31];
        __syncthreads();
    }
    if (tid == 0) off[N] = s_carry;
}

// ---------------------------------------------------------------------------
// Bucket fill: csrc[pos(dst)] = src
// ---------------------------------------------------------------------------
__global__ void fill_kernel(const void* __restrict__ ei, int E,
                            int* __restrict__ cur, int* __restrict__ csrc) {
    int i = blockIdx.x * blockDim.x + threadIdx.x;
    if (i >= E) return;
    int ss, dd;
    if (g_is64) {
        const long long* e = reinterpret_cast<const long long*>(ei);
        ss = (int)e[i];
        dd = (int)e[(size_t)E + i];
    } else {
        const int* e = reinterpret_cast<const int*>(ei);
        ss = e[i];
        dd = e[(size_t)E + i];
    }
    int pos = atomicAdd(cur + dd, 1);
    csrc[pos] = ss;
}

// ---------------------------------------------------------------------------
// Gather-side aggregation: one warp per node.
// h[i] = (1+eps)*x[i] + sum_j x[csrc[j]]  — plain stores, no atomics.
// ---------------------------------------------------------------------------
__global__ void agg_kernel(const float* __restrict__ x,
                           const int* __restrict__ csrc,
                           const int* __restrict__ off,
                           float* __restrict__ h, int N) {
    int w = (blockIdx.x * blockDim.x + threadIdx.x) >> 5;
    int lane = threadIdx.x & 31;
    if (w >= N) return;

    float4 acc = *reinterpret_cast<const float4*>(x + (size_t)w * D + lane * 4);
    const float sc = 1.0f + EPS;
    acc.x *= sc; acc.y *= sc; acc.z *= sc; acc.w *= sc;

    int j = off[w];
    const int e = off[w + 1];
    for (; j + 4 <= e; j += 4) {
        int a0 = __ldg(csrc + j), a1 = __ldg(csrc + j + 1);
        int a2 = __ldg(csrc + j + 2), a3 = __ldg(csrc + j + 3);
        float4 v0 = *reinterpret_cast<const float4*>(x + (size_t)a0 * D + lane * 4);
        float4 v1 = *reinterpret_cast<const float4*>(x + (size_t)a1 * D + lane * 4);
        float4 v2 = *reinterpret_cast<const float4*>(x + (size_t)a2 * D + lane * 4);
        float4 v3 = *reinterpret_cast<const float4*>(x + (size_t)a3 * D + lane * 4);
        acc.x += (v0.x + v1.x) + (v2.x + v3.x);
        acc.y += (v0.y + v1.y) + (v2.y + v3.y);
        acc.z += (v0.z + v1.z) + (v2.z + v3.z);
        acc.w += (v0.w + v1.w) + (v2.w + v3.w);
    }
    for (; j < e; j++) {
        int a0 = __ldg(csrc + j);
        float4 v0 = *reinterpret_cast<const float4*>(x + (size_t)a0 * D + lane * 4);
        acc.x += v0.x; acc.y += v0.y; acc.z += v0.z; acc.w += v0.w;
    }
    *reinterpret_cast<float4*>(h + (size_t)w * D + lane * 4) = acc;
}

// ---------------------------------------------------------------------------
// Fused MLP: out = relu(H @ W1 + b1) @ W2 + b2, per 128-row tile.
// GEMM1 -> h1 tile kept in SMEM (Hs) -> GEMM2. 256 threads, 8x8 micro-tiles,
// float4 LDS in the inner loops.
// ---------------------------------------------------------------------------
__global__ void __launch_bounds__(256, 2)
mlp_kernel(const float* __restrict__ H, const float* __restrict__ W1,
           const float* __restrict__ b1, const float* __restrict__ W2,
           const float* __restrict__ b2, float* __restrict__ out, int M) {
    extern __shared__ float sm[];
    float* As = sm;                    // [16][132] k-major A chunk
    float* Bs = As + 16 * 132;         // [16][128] weight chunk
    float* Hs = Bs + 16 * 128;         // [128][132] h1 tile (row-major, padded)

    const int tx = threadIdx.x & 15;
    const int ty = threadIdx.x >> 4;
    const int row0 = blockIdx.x * 128 + ty * 8;
    const int col0 = tx * 8;

    float acc[8][8];
    #pragma unroll
    for (int i = 0; i < 8; i++)
        #pragma unroll
        for (int j = 0; j < 8; j++) acc[i][j] = 0.0f;

    // ---------------- GEMM1: acc = H_tile @ W1 ----------------
    for (int kk = 0; kk < 128; kk += 16) {
        #pragma unroll
        for (int i = 0; i < 2; i++) {
            int f = threadIdx.x * 2 + i;           // 0..511
            int m  = f >> 2;
            int kq = f & 3;
            int grow = blockIdx.x * 128 + m;
            float4 va = make_float4(0.f, 0.f, 0.f, 0.f);
            if (grow < M)
                va = *reinterpret_cast<const float4*>(H + (size_t)grow * D + kk + kq * 4);
            As[(kq * 4 + 0) * 132 + m] = va.x;
            As[(kq * 4 + 1) * 132 + m] = va.y;
            As[(kq * 4 + 2) * 132 + m] = va.z;
            As[(kq * 4 + 3) * 132 + m] = va.w;
            int kb = f >> 5;
            int n4 = f & 31;
            *reinterpret_cast<float4*>(Bs + kb * 128 + n4 * 4) =
                *reinterpret_cast<const float4*>(W1 + (size_t)(kk + kb) * D + n4 * 4);
        }
        __syncthreads();

        #pragma unroll
        for (int k = 0; k < 16; k++) {
            float4 a01 = *reinterpret_cast<const float4*>(As + k * 132 + ty * 8);
            float4 a23 = *reinterpret_cast<const float4*>(As + k * 132 + ty * 8 + 4);
            float4 b01 = *reinterpret_cast<const float4*>(Bs + k * 128 + col0);
            float4 b23 = *reinterpret_cast<const float4*>(Bs + k * 128 + col0 + 4);
            float a[8] = {a01.x, a01.y, a01.z, a01.w, a23.x, a23.y, a23.z, a23.w};
            float b[8] = {b01.x, b01.y, b01.z, b01.w, b23.x, b23.y, b23.z, b23.w};
            #pragma unroll
            for (int i = 0; i < 8; i++)
                #pragma unroll
                for (int j = 0; j < 8; j++)
                    acc[i][j] = fmaf(a[i], b[j], acc[i][j]);
        }
        __syncthreads();
    }

    // Epilogue 1: bias + relu -> Hs[m][k2]
    {
        float bv[8];
        #pragma unroll
        for (int j = 0; j < 8; j++) bv[j] = b1[col0 + j];
        #pragma unroll
        for (int i = 0; i < 8; i++) {
            int row = ty * 8 + i;
            float4 o0, o1;
            o0.x = fmaxf(acc[i][0] + bv[0], 0.f);
            o0.y = fmaxf(acc[i][1] + bv[1], 0.f);
            o0.z = fmaxf(acc[i][2] + bv[2], 0.f);
            o0.w = fmaxf(acc[i][3] + bv[3], 0.f);
            o1.x = fmaxf(acc[i][4] + bv[4], 0.f);
            o1.y = fmaxf(acc[i][5] + bv[5], 0.f);
            o1.z = fmaxf(acc[i][6] + bv[6], 0.f);
            o1.w = fmaxf(acc[i][7] + bv[7], 0.f);
            *reinterpret_cast<float4*>(Hs + row * 132 + col0)     = o0;
            *reinterpret_cast<float4*>(Hs + row * 132 + col0 + 4) = o1;
            #pragma unroll
            for (int j = 0; j < 8; j++) acc[i][j] = 0.0f;
        }
    }
    __syncthreads();

    // ---------------- GEMM2: acc = Hs @ W2 ----------------
    for (int kk = 0; kk < 128; kk += 16) {
        #pragma unroll
        for (int i = 0; i < 2; i++) {
            int f = threadIdx.x * 2 + i;
            int kb = f >> 5;
            int n4 = f & 31;
            *reinterpret_cast<float4*>(Bs + kb * 128 + n4 * 4) =
                *reinterpret_cast<const float4*>(W2 + (size_t)(kk + kb) * D + n4 * 4);
        }
        __syncthreads();

        #pragma unroll
        for (int k = 0; k < 16; k++) {
            float a[8];
            #pragma unroll
            for (int i = 0; i < 8; i++)
                a[i] = Hs[(ty * 8 + i) * 132 + kk + k];   // broadcast across tx
            float4 b01 = *reinterpret_cast<const float4*>(Bs + k * 128 + col0);
            float4 b23 = *reinterpret_cast<const float4*>(Bs + k * 128 + col0 + 4);
            float b[8] = {b01.x, b01.y, b01.z, b01.w, b23.x, b23.y, b23.z, b23.w};
            #pragma unroll
            for (int i = 0; i < 8; i++)
                #pragma unroll
                for (int j = 0; j < 8; j++)
                    acc[i][j] = fmaf(a[i], b[j], acc[i][j]);
        }
        __syncthreads();
    }

    // Epilogue 2: bias -> global out
    {
        float bv[8];
        #pragma unroll
        for (int j = 0; j < 8; j++) bv[j] = b2[col0 + j];
        #pragma unroll
        for (int i = 0; i < 8; i++) {
            int r = row0 + i;
            if (r < M) {
                float4 o0, o1;
                o0.x = acc[i][0] + bv[0];
                o0.y = acc[i][1] + bv[1];
                o0.z = acc[i][2] + bv[2];
                o0.w = acc[i][3] + bv[3];
                o1.x = acc[i][4] + bv[4];
                o1.y = acc[i][5] + bv[5];
                o1.z = acc[i][6] + bv[6];
                o1.w = acc[i][7] + bv[7];
                *reinterpret_cast<float4*>(out + (size_t)r * D + col0)     = o0;
                *reinterpret_cast<float4*>(out + (size_t)r * D + col0 + 4) = o1;
            }
        }
    }
}

extern "C" void kernel_launch(void* const* d_in, const int* in_sizes, int n_in,
                              void* d_out, int out_size) {
    const float* x  = (const float*)d_in[0];
    const void*  ei = d_in[1];
    const float* W1 = (const float*)d_in[2];
    const float* b1 = (const float*)d_in[3];
    const float* W2 = (const float*)d_in[4];
    const float* b2 = (const float*)d_in[5];
    float* out = (float*)d_out;

    const int N = in_sizes[0] / D;
    const int E = in_sizes[1] / 2;

    // Device addresses of scratch symbols (host shadow would silently alias
    // host memory via ATS — the R1 bug).
    float* p_h    = nullptr;
    int*   p_deg  = nullptr;
    int*   p_off  = nullptr;
    int*   p_cur  = nullptr;
    int*   p_csrc = nullptr;
    cudaGetSymbolAddress((void**)(&p_h),    g_h);
    cudaGetSymbolAddress((void**)(&p_deg),  g_degcnt);
    cudaGetSymbolAddress((void**)(&p_off),  g_off);
    cudaGetSymbolAddress((void**)(&p_cur),  g_cur);
    cudaGetSymbolAddress((void**)(&p_csrc), g_csrc);

    const int smem_mlp = (16 * 132 + 16 * 128 + 128 * 132) * (int)sizeof(float);
    static int attr_set = 0;
    if (!attr_set) {
        cudaFuncSetAttribute(mlp_kernel,
                             cudaFuncAttributeMaxDynamicSharedMemorySize,
                             smem_mlp);
        attr_set = 1;
    }

    // 1) edge index width
    detect_kernel<<<1, 32>>>((const int*)ei);

    // 2) CSR build: zero -> histogram -> scan -> fill
    zero_deg_kernel<<<(N + 255) / 256, 256>>>(p_deg, N);
    hist_kernel<<<(E + 255) / 256, 256>>>(ei, E, p_deg);
    scan_kernel<<<1, 1024>>>(p_deg, p_off, p_cur, N);
    fill_kernel<<<(E + 255) / 256, 256>>>(ei, E, p_cur, p_csrc);

    // 3) gather aggregation (fuses (1+eps)*x init), warp per node
    agg_kernel<<<(N + 7) / 8, 256>>>(x, p_csrc, p_off, p_h, N);

    // 4) fused MLP (both GEMMs, h1 tile in SMEM)
    int gblocks = (N + 127) / 128;
    mlp_kernel<<<gblocks, 256, smem_mlp>>>(p_h, W1, b1, W2, b2, out, N);
}

// round 5
// speedup vs baseline: 1.5574x; 1.1399x over previous
#include <cuda_runtime.h>
#include <cstdint>

#define N_NODES 50000
#define N_EDGES_MAX 1600000
#define D 128
#define EPS 0.001f
#define SCAN_BLOCKS ((N_NODES + 1023) / 1024 + 1)   // 49 + 1 slot for total

// Scratch (allocation-free rule: __device__ globals)
__device__ float g_h[(size_t)N_NODES * D];      // (1+eps)*x + segment_sum
__device__ int   g_degcnt[N_NODES];             // per-dst degree
__device__ int   g_off[N_NODES + 1];            // CSR offsets
__device__ int   g_cur[N_NODES];                // fill cursors
__device__ int   g_csrc[N_EDGES_MAX];           // src ids bucketed by dst
__device__ int   g_bsum[SCAN_BLOCKS];           // per-block scan totals (+1)
__device__ int   g_is64;                        // edge_index width flag

// ---------------------------------------------------------------------------
// Detect whether edge_index is int64 or int32 (JAX x64-flag ambiguity).
// ---------------------------------------------------------------------------
__global__ void detect_kernel(const int* __restrict__ e32) {
    if (threadIdx.x == 0 && blockIdx.x == 0) {
        int is64 = 1;
        #pragma unroll 1
        for (int k = 1; k < 128; k += 2) {
            if (e32[k] != 0) { is64 = 0; break; }
        }
        g_is64 = is64;
    }
}

__global__ void zero_deg_kernel(int* __restrict__ degcnt, int n) {
    int i = blockIdx.x * blockDim.x + threadIdx.x;
    if (i < n) degcnt[i] = 0;
}

// ---------------------------------------------------------------------------
// Histogram of dst
// ---------------------------------------------------------------------------
__global__ void hist_kernel(const void* __restrict__ ei, int E,
                            int* __restrict__ degcnt) {
    int i = blockIdx.x * blockDim.x + threadIdx.x;
    if (i >= E) return;
    int dd;
    if (g_is64) dd = (int)reinterpret_cast<const long long*>(ei)[(size_t)E + i];
    else        dd = reinterpret_cast<const int*>(ei)[(size_t)E + i];
    atomicAdd(degcnt + dd, 1);
}

// ---------------------------------------------------------------------------
// Decoupled 3-phase exclusive scan of degcnt[0..N) into off[]/cur[].
// ---------------------------------------------------------------------------
__global__ void scan_part_kernel(const int* __restrict__ degcnt,
                                 int* __restrict__ off,
                                 int* __restrict__ bsum, int N) {
    __shared__ int wsum[32];
    const int tid = threadIdx.x, lane = tid & 31, wid = tid >> 5;
    int idx = blockIdx.x * 1024 + tid;
    int v = (idx < N) ? degcnt[idx] : 0;
    int incl = v;
    #pragma unroll
    for (int o = 1; o < 32; o <<= 1) {
        int t = __shfl_up_sync(0xffffffffu, incl, o);
        if (lane >= o) incl += t;
    }
    if (lane == 31) wsum[wid] = incl;
    __syncthreads();
    if (wid == 0) {
        int s = wsum[lane];
        #pragma unroll
        for (int o = 1; o < 32; o <<= 1) {
            int t = __shfl_up_sync(0xffffffffu, s, o);
            if (lane >= o) s += t;
        }
        wsum[lane] = s;
    }
    __syncthreads();
    int woff = wid ? wsum[wid - 1] : 0;
    if (idx < N) off[idx] = woff + incl - v;          // local exclusive prefix
    if (tid == 1023) bsum[blockIdx.x] = woff + incl;  // block total
}

__global__ void scan_tops_kernel(int* __restrict__ bsum, int nb) {
    // nb <= 63: two-warp scan
    const int tid = threadIdx.x, lane = tid & 31;
    int v = (tid < nb) ? bsum[tid] : 0;
    int incl = v;
    #pragma unroll
    for (int o = 1; o < 32; o <<= 1) {
        int t = __shfl_up_sync(0xffffffffu, incl, o);
        if (lane >= o) incl += t;
    }
    __shared__ int w0_total;
    if (tid == 31) w0_total = incl;
    __syncthreads();
    int base = (tid >= 32) ? w0_total : 0;
    if (tid < nb) bsum[tid] = base + incl - v;        // exclusive
    if (tid == nb - 1) bsum[nb] = base + incl;        // grand total at [nb]
}

__global__ void scan_add_kernel(int* __restrict__ off, int* __restrict__ cur,
                                const int* __restrict__ bsum, int N, int nb) {
    int idx = blockIdx.x * 1024 + threadIdx.x;
    if (idx < N) {
        int v = off[idx] + bsum[blockIdx.x];
        off[idx] = v;
        cur[idx] = v;
    }
    if (idx == 0) off[N] = bsum[nb];
}

// ---------------------------------------------------------------------------
// Bucket fill: csrc[pos(dst)] = src
// ---------------------------------------------------------------------------
__global__ void fill_kernel(const void* __restrict__ ei, int E,
                            int* __restrict__ cur, int* __restrict__ csrc) {
    int i = blockIdx.x * blockDim.x + threadIdx.x;
    if (i >= E) return;
    int ss, dd;
    if (g_is64) {
        const long long* e = reinterpret_cast<const long long*>(ei);
        ss = (int)e[i];
        dd = (int)e[(size_t)E + i];
    } else {
        const int* e = reinterpret_cast<const int*>(ei);
        ss = e[i];
        dd = e[(size_t)E + i];
    }
    int pos = atomicAdd(cur + dd, 1);
    csrc[pos] = ss;
}

// ---------------------------------------------------------------------------
// Gather-side aggregation: one warp per node.
// ---------------------------------------------------------------------------
__global__ void agg_kernel(const float* __restrict__ x,
                           const int* __restrict__ csrc,
                           const int* __restrict__ off,
                           float* __restrict__ h, int N) {
    int w = (blockIdx.x * blockDim.x + threadIdx.x) >> 5;
    int lane = threadIdx.x & 31;
    if (w >= N) return;

    float4 acc = *reinterpret_cast<const float4*>(x + (size_t)w * D + lane * 4);
    const float sc = 1.0f + EPS;
    acc.x *= sc; acc.y *= sc; acc.z *= sc; acc.w *= sc;

    int j = off[w];
    const int e = off[w + 1];
    for (; j + 4 <= e; j += 4) {
        int a0 = __ldg(csrc + j), a1 = __ldg(csrc + j + 1);
        int a2 = __ldg(csrc + j + 2), a3 = __ldg(csrc + j + 3);
        float4 v0 = *reinterpret_cast<const float4*>(x + (size_t)a0 * D + lane * 4);
        float4 v1 = *reinterpret_cast<const float4*>(x + (size_t)a1 * D + lane * 4);
        float4 v2 = *reinterpret_cast<const float4*>(x + (size_t)a2 * D + lane * 4);
        float4 v3 = *reinterpret_cast<const float4*>(x + (size_t)a3 * D + lane * 4);
        acc.x += (v0.x + v1.x) + (v2.x + v3.x);
        acc.y += (v0.y + v1.y) + (v2.y + v3.y);
        acc.z += (v0.z + v1.z) + (v2.z + v3.z);
        acc.w += (v0.w + v1.w) + (v2.w + v3.w);
    }
    for (; j < e; j++) {
        int a0 = __ldg(csrc + j);
        float4 v0 = *reinterpret_cast<const float4*>(x + (size_t)a0 * D + lane * 4);
        acc.x += v0.x; acc.y += v0.y; acc.z += v0.z; acc.w += v0.w;
    }
    *reinterpret_cast<float4*>(h + (size_t)w * D + lane * 4) = acc;
}

// ---------------------------------------------------------------------------
// Fused MLP: out = relu(H @ W1 + b1) @ W2 + b2, per 128-row tile.
// ---------------------------------------------------------------------------
__global__ void __launch_bounds__(256, 2)
mlp_kernel(const float* __restrict__ H, const float* __restrict__ W1,
           const float* __restrict__ b1, const float* __restrict__ W2,
           const float* __restrict__ b2, float* __restrict__ out, int M) {
    extern __shared__ float sm[];
    float* As = sm;                    // [16][132]
    float* Bs = As + 16 * 132;         // [16][128]
    float* Hs = Bs + 16 * 128;         // [128][132]

    const int tx = threadIdx.x & 15;
    const int ty = threadIdx.x >> 4;
    const int row0 = blockIdx.x * 128 + ty * 8;
    const int col0 = tx * 8;

    float acc[8][8];
    #pragma unroll
    for (int i = 0; i < 8; i++)
        #pragma unroll
        for (int j = 0; j < 8; j++) acc[i][j] = 0.0f;

    for (int kk = 0; kk < 128; kk += 16) {
        #pragma unroll
        for (int i = 0; i < 2; i++) {
            int f = threadIdx.x * 2 + i;
            int m  = f >> 2;
            int kq = f & 3;
            int grow = blockIdx.x * 128 + m;
            float4 va = make_float4(0.f, 0.f, 0.f, 0.f);
            if (grow < M)
                va = *reinterpret_cast<const float4*>(H + (size_t)grow * D + kk + kq * 4);
            As[(kq * 4 + 0) * 132 + m] = va.x;
            As[(kq * 4 + 1) * 132 + m] = va.y;
            As[(kq * 4 + 2) * 132 + m] = va.z;
            As[(kq * 4 + 3) * 132 + m] = va.w;
            int kb = f >> 5;
            int n4 = f & 31;
            *reinterpret_cast<float4*>(Bs + kb * 128 + n4 * 4) =
                *reinterpret_cast<const float4*>(W1 + (size_t)(kk + kb) * D + n4 * 4);
        }
        __syncthreads();

        #pragma unroll
        for (int k = 0; k < 16; k++) {
            float4 a01 = *reinterpret_cast<const float4*>(As + k * 132 + ty * 8);
            float4 a23 = *reinterpret_cast<const float4*>(As + k * 132 + ty * 8 + 4);
            float4 b01 = *reinterpret_cast<const float4*>(Bs + k * 128 + col0);
            float4 b23 = *reinterpret_cast<const float4*>(Bs + k * 128 + col0 + 4);
            float a[8] = {a01.x, a01.y, a01.z, a01.w, a23.x, a23.y, a23.z, a23.w};
            float b[8] = {b01.x, b01.y, b01.z, b01.w, b23.x, b23.y, b23.z, b23.w};
            #pragma unroll
            for (int i = 0; i < 8; i++)
                #pragma unroll
                for (int j = 0; j < 8; j++)
                    acc[i][j] = fmaf(a[i], b[j], acc[i][j]);
        }
        __syncthreads();
    }

    {
        float bv[8];
        #pragma unroll
        for (int j = 0; j < 8; j++) bv[j] = b1[col0 + j];
        #pragma unroll
        for (int i = 0; i < 8; i++) {
            int row = ty * 8 + i;
            float4 o0, o1;
            o0.x = fmaxf(acc[i][0] + bv[0], 0.f);
            o0.y = fmaxf(acc[i][1] + bv[1], 0.f);
            o0.z = fmaxf(acc[i][2] + bv[2], 0.f);
            o0.w = fmaxf(acc[i][3] + bv[3], 0.f);
            o1.x = fmaxf(acc[i][4] + bv[4], 0.f);
            o1.y = fmaxf(acc[i][5] + bv[5], 0.f);
            o1.z = fmaxf(acc[i][6] + bv[6], 0.f);
            o1.w = fmaxf(acc[i][7] + bv[7], 0.f);
            *reinterpret_cast<float4*>(Hs + row * 132 + col0)     = o0;
            *reinterpret_cast<float4*>(Hs + row * 132 + col0 + 4) = o1;
            #pragma unroll
            for (int j = 0; j < 8; j++) acc[i][j] = 0.0f;
        }
    }
    __syncthreads();

    for (int kk = 0; kk < 128; kk += 16) {
        #pragma unroll
        for (int i = 0; i < 2; i++) {
            int f = threadIdx.x * 2 + i;
            int kb = f >> 5;
            int n4 = f & 31;
            *reinterpret_cast<float4*>(Bs + kb * 128 + n4 * 4) =
                *reinterpret_cast<const float4*>(W2 + (size_t)(kk + kb) * D + n4 * 4);
        }
        __syncthreads();

        #pragma unroll
        for (int k = 0; k < 16; k++) {
            float a[8];
            #pragma unroll
            for (int i = 0; i < 8; i++)
                a[i] = Hs[(ty * 8 + i) * 132 + kk + k];
            float4 b01 = *reinterpret_cast<const float4*>(Bs + k * 128 + col0);
            float4 b23 = *reinterpret_cast<const float4*>(Bs + k * 128 + col0 + 4);
            float b[8] = {b01.x, b01.y, b01.z, b01.w, b23.x, b23.y, b23.z, b23.w};
            #pragma unroll
            for (int i = 0; i < 8; i++)
                #pragma unroll
                for (int j = 0; j < 8; j++)
                    acc[i][j] = fmaf(a[i], b[j], acc[i][j]);
        }
        __syncthreads();
    }

    {
        float bv[8];
        #pragma unroll
        for (int j = 0; j < 8; j++) bv[j] = b2[col0 + j];
        #pragma unroll
        for (int i = 0; i < 8; i++) {
            int r = row0 + i;
            if (r < M) {
                float4 o0, o1;
                o0.x = acc[i][0] + bv[0];
                o0.y = acc[i][1] + bv[1];
                o0.z = acc[i][2] + bv[2];
                o0.w = acc[i][3] + bv[3];
                o1.x = acc[i][4] + bv[4];
                o1.y = acc[i][5] + bv[5];
                o1.z = acc[i][6] + bv[6];
                o1.w = acc[i][7] + bv[7];
                *reinterpret_cast<float4*>(out + (size_t)r * D + col0)     = o0;
                *reinterpret_cast<float4*>(out + (size_t)r * D + col0 + 4) = o1;
            }
        }
    }
}

extern "C" void kernel_launch(void* const* d_in, const int* in_sizes, int n_in,
                              void* d_out, int out_size) {
    const float* x  = (const float*)d_in[0];
    const void*  ei = d_in[1];
    const float* W1 = (const float*)d_in[2];
    const float* b1 = (const float*)d_in[3];
    const float* W2 = (const float*)d_in[4];
    const float* b2 = (const float*)d_in[5];
    float* out = (float*)d_out;

    const int N = in_sizes[0] / D;
    const int E = in_sizes[1] / 2;
    const int nb = (N + 1023) / 1024;   // 49

    float* p_h    = nullptr;
    int*   p_deg  = nullptr;
    int*   p_off  = nullptr;
    int*   p_cur  = nullptr;
    int*   p_csrc = nullptr;
    int*   p_bsum = nullptr;
    cudaGetSymbolAddress((void**)(&p_h),    g_h);
    cudaGetSymbolAddress((void**)(&p_deg),  g_degcnt);
    cudaGetSymbolAddress((void**)(&p_off),  g_off);
    cudaGetSymbolAddress((void**)(&p_cur),  g_cur);
    cudaGetSymbolAddress((void**)(&p_csrc), g_csrc);
    cudaGetSymbolAddress((void**)(&p_bsum), g_bsum);

    const int smem_mlp = (16 * 132 + 16 * 128 + 128 * 132) * (int)sizeof(float);
    static int attr_set = 0;
    if (!attr_set) {
        cudaFuncSetAttribute(mlp_kernel,
                             cudaFuncAttributeMaxDynamicSharedMemorySize,
                             smem_mlp);
        attr_set = 1;
    }

    detect_kernel<<<1, 32>>>((const int*)ei);

    zero_deg_kernel<<<(N + 255) / 256, 256>>>(p_deg, N);
    hist_kernel<<<(E + 255) / 256, 256>>>(ei, E, p_deg);
    scan_part_kernel<<<nb, 1024>>>(p_deg, p_off, p_bsum, N);
    scan_tops_kernel<<<1, 64>>>(p_bsum, nb);
    scan_add_kernel<<<nb, 1024>>>(p_off, p_cur, p_bsum, N, nb);
    fill_kernel<<<(E + 255) / 256, 256>>>(ei, E, p_cur, p_csrc);

    agg_kernel<<<(N + 7) / 8, 256>>>(x, p_csrc, p_off, p_h, N);

    int gblocks = (N + 127) / 128;
    mlp_kernel<<<gblocks, 256, smem_mlp>>>(p_h, W1, b1, W2, b2, out, N);
}

// round 7
// speedup vs baseline: 1.5972x; 1.0255x over previous
#include <cuda_runtime.h>
#include <cstdint>

#define N_NODES 50000
#define N_EDGES_MAX 1600000
#define D 128
#define EPS 0.001f
#define SCAN_BLOCKS ((N_NODES + 1023) / 1024 + 1)

// Scratch (allocation-free rule: __device__ globals)
__device__ float g_h[(size_t)N_NODES * D];
__device__ int   g_degcnt[N_NODES];
__device__ int   g_off[N_NODES + 1];
__device__ int   g_cur[N_NODES];
__device__ int   g_csrc[N_EDGES_MAX];
__device__ int   g_bsum[SCAN_BLOCKS];
__device__ int   g_is64;

// Packed f32x2 FMA (family-common on sm_100+; FFMA2 in SASS, PTX-only path)
__device__ __forceinline__ void ffma2(unsigned long long& d,
                                      unsigned long long a,
                                      unsigned long long b) {
    asm("fma.rn.f32x2 %0, %1, %2, %0;" : "+l"(d) : "l"(a), "l"(b));
}
__device__ __forceinline__ unsigned long long pack_dup(float v) {
    unsigned long long p;
    asm("mov.b64 %0, {%1, %1};" : "=l"(p) : "r"(__float_as_uint(v)));
    return p;
}
__device__ __forceinline__ void unpack2(unsigned long long p, float& lo, float& hi) {
    uint32_t a, b;
    asm("mov.b64 {%0, %1}, %2;" : "=r"(a), "=r"(b) : "l"(p));
    lo = __uint_as_float(a);
    hi = __uint_as_float(b);
}

// ===========================================================================
// CSR build + aggregation (unchanged from R5 — passed at 2.7e-7)
// ===========================================================================
__global__ void detect_kernel(const int* __restrict__ e32) {
    if (threadIdx.x == 0 && blockIdx.x == 0) {
        int is64 = 1;
        #pragma unroll 1
        for (int k = 1; k < 128; k += 2) {
            if (e32[k] != 0) { is64 = 0; break; }
        }
        g_is64 = is64;
    }
}

__global__ void zero_deg_kernel(int* __restrict__ degcnt, int n) {
    int i = blockIdx.x * blockDim.x + threadIdx.x;
    if (i < n) degcnt[i] = 0;
}

__global__ void hist_kernel(const void* __restrict__ ei, int E,
                            int* __restrict__ degcnt) {
    int i = blockIdx.x * blockDim.x + threadIdx.x;
    if (i >= E) return;
    int dd;
    if (g_is64) dd = (int)reinterpret_cast<const long long*>(ei)[(size_t)E + i];
    else        dd = reinterpret_cast<const int*>(ei)[(size_t)E + i];
    atomicAdd(degcnt + dd, 1);
}

__global__ void scan_part_kernel(const int* __restrict__ degcnt,
                                 int* __restrict__ off,
                                 int* __restrict__ bsum, int N) {
    __shared__ int wsum[32];
    const int tid = threadIdx.x, lane = tid & 31, wid = tid >> 5;
    int idx = blockIdx.x * 1024 + tid;
    int v = (idx < N) ? degcnt[idx] : 0;
    int incl = v;
    #pragma unroll
    for (int o = 1; o < 32; o <<= 1) {
        int t = __shfl_up_sync(0xffffffffu, incl, o);
        if (lane >= o) incl += t;
    }
    if (lane == 31) wsum[wid] = incl;
    __syncthreads();
    if (wid == 0) {
        int s = wsum[lane];
        #pragma unroll
        for (int o = 1; o < 32; o <<= 1) {
            int t = __shfl_up_sync(0xffffffffu, s, o);
            if (lane >= o) s += t;
        }
        wsum[lane] = s;
    }
    __syncthreads();
    int woff = wid ? wsum[wid - 1] : 0;
    if (idx < N) off[idx] = woff + incl - v;
    if (tid == 1023) bsum[blockIdx.x] = woff + incl;
}

__global__ void scan_tops_kernel(int* __restrict__ bsum, int nb) {
    const int tid = threadIdx.x, lane = tid & 31;
    int v = (tid < nb) ? bsum[tid] : 0;
    int incl = v;
    #pragma unroll
    for (int o = 1; o < 32; o <<= 1) {
        int t = __shfl_up_sync(0xffffffffu, incl, o);
        if (lane >= o) incl += t;
    }
    __shared__ int w0_total;
    if (tid == 31) w0_total = incl;
    __syncthreads();
    int base = (tid >= 32) ? w0_total : 0;
    if (tid < nb) bsum[tid] = base + incl - v;
    if (tid == nb - 1) bsum[nb] = base + incl;
}

__global__ void scan_add_kernel(int* __restrict__ off, int* __restrict__ cur,
                                const int* __restrict__ bsum, int N, int nb) {
    int idx = blockIdx.x * 1024 + threadIdx.x;
    if (idx < N) {
        int v = off[idx] + bsum[blockIdx.x];
        off[idx] = v;
        cur[idx] = v;
    }
    if (idx == 0) off[N] = bsum[nb];
}

__global__ void fill_kernel(const void* __restrict__ ei, int E,
                            int* __restrict__ cur, int* __restrict__ csrc) {
    int i = blockIdx.x * blockDim.x + threadIdx.x;
    if (i >= E) return;
    int ss, dd;
    if (g_is64) {
        const long long* e = reinterpret_cast<const long long*>(ei);
        ss = (int)e[i];
        dd = (int)e[(size_t)E + i];
    } else {
        const int* e = reinterpret_cast<const int*>(ei);
        ss = e[i];
        dd = e[(size_t)E + i];
    }
    int pos = atomicAdd(cur + dd, 1);
    csrc[pos] = ss;
}

__global__ void agg_kernel(const float* __restrict__ x,
                           const int* __restrict__ csrc,
                           const int* __restrict__ off,
                           float* __restrict__ h, int N) {
    int w = (blockIdx.x * blockDim.x + threadIdx.x) >> 5;
    int lane = threadIdx.x & 31;
    if (w >= N) return;

    float4 acc = *reinterpret_cast<const float4*>(x + (size_t)w * D + lane * 4);
    const float sc = 1.0f + EPS;
    acc.x *= sc; acc.y *= sc; acc.z *= sc; acc.w *= sc;

    int j = off[w];
    const int e = off[w + 1];
    for (; j + 4 <= e; j += 4) {
        int a0 = __ldg(csrc + j), a1 = __ldg(csrc + j + 1);
        int a2 = __ldg(csrc + j + 2), a3 = __ldg(csrc + j + 3);
        float4 v0 = *reinterpret_cast<const float4*>(x + (size_t)a0 * D + lane * 4);
        float4 v1 = *reinterpret_cast<const float4*>(x + (size_t)a1 * D + lane * 4);
        float4 v2 = *reinterpret_cast<const float4*>(x + (size_t)a2 * D + lane * 4);
        float4 v3 = *reinterpret_cast<const float4*>(x + (size_t)a3 * D + lane * 4);
        acc.x += (v0.x + v1.x) + (v2.x + v3.x);
        acc.y += (v0.y + v1.y) + (v2.y + v3.y);
        acc.z += (v0.z + v1.z) + (v2.z + v3.z);
        acc.w += (v0.w + v1.w) + (v2.w + v3.w);
    }
    for (; j < e; j++) {
        int a0 = __ldg(csrc + j);
        float4 v0 = *reinterpret_cast<const float4*>(x + (size_t)a0 * D + lane * 4);
        acc.x += v0.x; acc.y += v0.y; acc.z += v0.z; acc.w += v0.w;
    }
    *reinterpret_cast<float4*>(h + (size_t)w * D + lane * 4) = acc;
}

// ===========================================================================
// Fused MLP with packed f32x2 FMA:
//   out = relu(H @ W1 + b1) @ W2 + b2, 128-row tile / CTA, 256 threads.
// Accumulators: 8 rows x 4 column-pairs of packed f32x2 (FFMA2).
// ===========================================================================
__global__ void __launch_bounds__(256, 2)
mlp_kernel(const float* __restrict__ H, const float* __restrict__ W1,
           const float* __restrict__ b1, const float* __restrict__ W2,
           const float* __restrict__ b2, float* __restrict__ out, int M) {
    extern __shared__ float sm[];
    float* As = sm;                    // [16][132] k-major A chunk
    float* Bs = As + 16 * 132;         // [16][128] weight chunk
    float* Hs = Bs + 16 * 128;         // [128][132] h1 tile

    const int tx = threadIdx.x & 15;
    const int ty = threadIdx.x >> 4;
    const int row0 = blockIdx.x * 128 + ty * 8;
    const int col0 = tx * 8;

    unsigned long long acc[8][4];
    #pragma unroll
    for (int i = 0; i < 8; i++)
        #pragma unroll
        for (int j = 0; j < 4; j++) acc[i][j] = 0ull;

    // ---------------- GEMM1: acc = H_tile @ W1 ----------------
    for (int kk = 0; kk < 128; kk += 16) {
        #pragma unroll
        for (int i = 0; i < 2; i++) {
            int f = threadIdx.x * 2 + i;           // 0..511
            int m  = f >> 2;
            int kq = f & 3;
            int grow = blockIdx.x * 128 + m;
            float4 va = make_float4(0.f, 0.f, 0.f, 0.f);
            if (grow < M)
                va = *reinterpret_cast<const float4*>(H + (size_t)grow * D + kk + kq * 4);
            As[(kq * 4 + 0) * 132 + m] = va.x;
            As[(kq * 4 + 1) * 132 + m] = va.y;
            As[(kq * 4 + 2) * 132 + m] = va.z;
            As[(kq * 4 + 3) * 132 + m] = va.w;
            int kb = f >> 5;
            int n4 = f & 31;
            *reinterpret_cast<float4*>(Bs + kb * 128 + n4 * 4) =
                *reinterpret_cast<const float4*>(W1 + (size_t)(kk + kb) * D + n4 * 4);
        }
        __syncthreads();

        #pragma unroll
        for (int k = 0; k < 16; k++) {
            float4 a01 = *reinterpret_cast<const float4*>(As + k * 132 + ty * 8);
            float4 a23 = *reinterpret_cast<const float4*>(As + k * 132 + ty * 8 + 4);
            const unsigned long long* bp =
                reinterpret_cast<const unsigned long long*>(Bs + k * 128 + col0);
            unsigned long long bv0 = bp[0], bv1 = bp[1], bv2 = bp[2], bv3 = bp[3];
            float a[8] = {a01.x, a01.y, a01.z, a01.w, a23.x, a23.y, a23.z, a23.w};
            #pragma unroll
            for (int i = 0; i < 8; i++) {
                unsigned long long ap = pack_dup(a[i]);
                ffma2(acc[i][0], ap, bv0);
                ffma2(acc[i][1], ap, bv1);
                ffma2(acc[i][2], ap, bv2);
                ffma2(acc[i][3], ap, bv3);
            }
        }
        __syncthreads();
    }

    // Epilogue 1: bias + relu -> Hs
    {
        float bv[8];
        #pragma unroll
        for (int j = 0; j < 8; j++) bv[j] = b1[col0 + j];
        #pragma unroll
        for (int i = 0; i < 8; i++) {
            int row = ty * 8 + i;
            float o[8];
            #pragma unroll
            for (int j = 0; j < 4; j++) {
                unpack2(acc[i][j], o[2 * j], o[2 * j + 1]);
                acc[i][j] = 0ull;
            }
            float4 o0, o1;
            o0.x = fmaxf(o[0] + bv[0], 0.f);
            o0.y = fmaxf(o[1] + bv[1], 0.f);
            o0.z = fmaxf(o[2] + bv[2], 0.f);
            o0.w = fmaxf(o[3] + bv[3], 0.f);
            o1.x = fmaxf(o[4] + bv[4], 0.f);
            o1.y = fmaxf(o[5] + bv[5], 0.f);
            o1.z = fmaxf(o[6] + bv[6], 0.f);
            o1.w = fmaxf(o[7] + bv[7], 0.f);
            *reinterpret_cast<float4*>(Hs + row * 132 + col0)     = o0;
            *reinterpret_cast<float4*>(Hs + row * 132 + col0 + 4) = o1;
        }
    }
    __syncthreads();

    // ---------------- GEMM2: acc = Hs @ W2 ----------------
    for (int kk = 0; kk < 128; kk += 16) {
        #pragma unroll
        for (int i = 0; i < 2; i++) {
            int f = threadIdx.x * 2 + i;
            int kb = f >> 5;
            int n4 = f & 31;
            *reinterpret_cast<float4*>(Bs + kb * 128 + n4 * 4) =
                *reinterpret_cast<const float4*>(W2 + (size_t)(kk + kb) * D + n4 * 4);
        }
        __syncthreads();

        #pragma unroll
        for (int k = 0; k < 16; k++) {
            const unsigned long long* bp =
                reinterpret_cast<const unsigned long long*>(Bs + k * 128 + col0);
            unsigned long long bv0 = bp[0], bv1 = bp[1], bv2 = bp[2], bv3 = bp[3];
            #pragma unroll
            for (int i = 0; i < 8; i++) {
                unsigned long long ap = pack_dup(Hs[(ty * 8 + i) * 132 + kk + k]);
                ffma2(acc[i][0], ap, bv0);
                ffma2(acc[i][1], ap, bv1);
                ffma2(acc[i][2], ap, bv2);
                ffma2(acc[i][3], ap, bv3);
            }
        }
        __syncthreads();
    }

    // Epilogue 2: bias -> global out
    {
        float bv[8];
        #pragma unroll
        for (int j = 0; j < 8; j++) bv[j] = b2[col0 + j];
        #pragma unroll
        for (int i = 0; i < 8; i++) {
            int r = row0 + i;
            if (r < M) {
                float o[8];
                #pragma unroll
                for (int j = 0; j < 4; j++)
                    unpack2(acc[i][j], o[2 * j], o[2 * j + 1]);
                float4 o0, o1;
                o0.x = o[0] + bv[0];
                o0.y = o[1] + bv[1];
                o0.z = o[2] + bv[2];
                o0.w = o[3] + bv[3];
                o1.x = o[4] + bv[4];
                o1.y = o[5] + bv[5];
                o1.z = o[6] + bv[6];
                o1.w = o[7] + bv[7];
                *reinterpret_cast<float4*>(out + (size_t)r * D + col0)     = o0;
                *reinterpret_cast<float4*>(out + (size_t)r * D + col0 + 4) = o1;
            }
        }
    }
}

extern "C" void kernel_launch(void* const* d_in, const int* in_sizes, int n_in,
                              void* d_out, int out_size) {
    const float* x  = (const float*)d_in[0];
    const void*  ei = d_in[1];
    const float* W1 = (const float*)d_in[2];
    const float* b1 = (const float*)d_in[3];
    const float* W2 = (const float*)d_in[4];
    const float* b2 = (const float*)d_in[5];
    float* out = (float*)d_out;

    const int N = in_sizes[0] / D;
    const int E = in_sizes[1] / 2;
    const int nb = (N + 1023) / 1024;

    float* p_h    = nullptr;
    int*   p_deg  = nullptr;
    int*   p_off  = nullptr;
    int*   p_cur  = nullptr;
    int*   p_csrc = nullptr;
    int*   p_bsum = nullptr;
    cudaGetSymbolAddress((void**)(&p_h),    g_h);
    cudaGetSymbolAddress((void**)(&p_deg),  g_degcnt);
    cudaGetSymbolAddress((void**)(&p_off),  g_off);
    cudaGetSymbolAddress((void**)(&p_cur),  g_cur);
    cudaGetSymbolAddress((void**)(&p_csrc), g_csrc);
    cudaGetSymbolAddress((void**)(&p_bsum), g_bsum);

    const int smem_mlp = (16 * 132 + 16 * 128 + 128 * 132) * (int)sizeof(float);
    static int attr_set = 0;
    if (!attr_set) {
        cudaFuncSetAttribute(mlp_kernel,
                             cudaFuncAttributeMaxDynamicSharedMemorySize,
                             smem_mlp);
        attr_set = 1;
    }

    detect_kernel<<<1, 32>>>((const int*)ei);

    zero_deg_kernel<<<(N + 255) / 256, 256>>>(p_deg, N);
    hist_kernel<<<(E + 255) / 256, 256>>>(ei, E, p_deg);
    scan_part_kernel<<<nb, 1024>>>(p_deg, p_off, p_bsum, N);
    scan_tops_kernel<<<1, 64>>>(p_bsum, nb);
    scan_add_kernel<<<nb, 1024>>>(p_off, p_cur, p_bsum, N, nb);
    fill_kernel<<<(E + 255) / 256, 256>>>(ei, E, p_cur, p_csrc);

    agg_kernel<<<(N + 7) / 8, 256>>>(x, p_csrc, p_off, p_h, N);

    int gblocks = (N + 127) / 128;
    mlp_kernel<<<gblocks, 256, smem_mlp>>>(p_h, W1, b1, W2, b2, out, N);
}